// round 13
// baseline (speedup 1.0000x reference)
#include <cuda_runtime.h>
#include <math.h>
#include <stdint.h>

#define B_    32
#define S_    256
#define A_    6
#define H_    1024
#define OBS_  520
#define GLOB_ 30
#define MASK_ 52
#define AGF_  73
#define NSEQ  192          // B_*A_
#define KVEC  112          // 102 padded to mult of 16
#define EMBD  512
#define G3H   3072
#define MROWS 49152        // NSEQ*S_
#define NLOG  (B_*S_*MASK_)  // 425984

// ---------------- scratch (device globals; no allocations allowed) ----------------
__device__ float g_vec[(size_t)NSEQ * S_ * KVEC];
__device__ float g_wemb[5 * KVEC * EMBD];
__device__ int   g_types[NSEQ];
__device__ float g_emb[(size_t)MROWS * EMBD];
__device__ float g_xg[(size_t)MROWS * G3H];        // step-major: [s][n][3072]
__device__ float g_ha[NSEQ * H_];
__device__ float g_hb[NSEQ * H_];
__device__ float g_hg[NSEQ * G3H];
__device__ float g_hf[NSEQ * H_];
__device__ float g_g0[NSEQ * H_];
__device__ float g_g1[NSEQ * H_];
__device__ float g_logits[B_ * MASK_];

// ---------------- packed f32x2 helpers (FFMA2: 2x fp32 throughput on sm_103a) ------
__device__ __forceinline__ unsigned long long ffma2(unsigned long long a,
                                                    unsigned long long b,
                                                    unsigned long long c) {
    unsigned long long d;
    asm("fma.rn.f32x2 %0, %1, %2, %3;" : "=l"(d) : "l"(a), "l"(b), "l"(c));
    return d;
}
__device__ __forceinline__ unsigned long long pack2(float x, float y) {
    unsigned long long r;
    asm("mov.b64 %0, {%1, %2};" : "=l"(r) : "f"(x), "f"(y));
    return r;
}
__device__ __forceinline__ float2 unpack2(unsigned long long p) {
    float2 v;
    asm("mov.b64 {%0, %1}, %2;" : "=f"(v.x), "=f"(v.y) : "l"(p));
    return v;
}

// ---------------- generic tiled GEMM: C = A(MxK) * B + bias (opt relu) -------------
// BNT=true : B is (N,K) row-major (C = A * B^T)
// BNT=false: B is (K,N) row-major (C = A * B)
// ROW_REMAP: output row r -> (r%256)*NSEQ + r/256   (n-major -> step-major for xg)
// PER_TYPE : B/bias base advanced by types[m0/256] (embedding GEMM)
template <int BM, int BN, int TM, int TN, bool BNT, bool DO_RELU, bool ROW_REMAP, bool PER_TYPE>
__global__ void __launch_bounds__(256, 2)
gemm_kernel(const float* __restrict__ A, const float* __restrict__ Bm,
            const float* __restrict__ bias, float* __restrict__ C,
            int M, int N, int K, int lda, int ldb, int ldc,
            const int* __restrict__ types, long btstride, int biastride) {
    __shared__ __align__(16) float As[16][BM + 4];
    __shared__ __align__(16) float Bs[16][BN + 4];
    const int tid = threadIdx.x;
    const int m0 = blockIdx.y * BM;
    const int n0 = blockIdx.x * BN;

    const float* Bp = Bm;
    const float* biasp = bias;
    if (PER_TYPE) {
        int t = types[m0 >> 8];
        Bp += (long)t * btstride;
        biasp += (long)t * biastride;
    }

    const int TC = BN / TN;
    const int trow = tid / TC;
    const int tcol = tid % TC;

    unsigned long long acc[TM][TN / 2];
#pragma unroll
    for (int i = 0; i < TM; i++)
#pragma unroll
        for (int j = 0; j < TN / 2; j++) acc[i][j] = 0ULL;

    const int ktiles = K >> 4;
    for (int kt = 0; kt < ktiles; ++kt) {
        const int k0 = kt << 4;
        // load A tile (BM x 16), stored k-major
#pragma unroll
        for (int it = 0; it < (BM * 4) / 256; ++it) {
            int idx = tid + it * 256;
            int row = idx >> 2, kq = idx & 3;
            const float4 v = *(const float4*)(A + (long)(m0 + row) * lda + k0 + kq * 4);
            As[kq * 4 + 0][row] = v.x; As[kq * 4 + 1][row] = v.y;
            As[kq * 4 + 2][row] = v.z; As[kq * 4 + 3][row] = v.w;
        }
        if (BNT) {
#pragma unroll
            for (int it = 0; it < (BN * 4) / 256; ++it) {
                int idx = tid + it * 256;
                int row = idx >> 2, kq = idx & 3;
                const float4 v = *(const float4*)(Bp + (long)(n0 + row) * ldb + k0 + kq * 4);
                Bs[kq * 4 + 0][row] = v.x; Bs[kq * 4 + 1][row] = v.y;
                Bs[kq * 4 + 2][row] = v.z; Bs[kq * 4 + 3][row] = v.w;
            }
        } else {
#pragma unroll
            for (int it = 0; it < (BN * 4) / 256; ++it) {
                int idx = tid + it * 256;
                int kr = idx / (BN / 4), nq = idx % (BN / 4);
                *(float4*)&Bs[kr][nq * 4] =
                    *(const float4*)(Bp + (long)(k0 + kr) * ldb + n0 + nq * 4);
            }
        }
        __syncthreads();
#pragma unroll
        for (int k = 0; k < 16; k++) {
            float a[TM];
#pragma unroll
            for (int i = 0; i < TM; i += 4) {
                float4 v = *(const float4*)&As[k][trow * TM + i];
                a[i] = v.x; a[i + 1] = v.y; a[i + 2] = v.z; a[i + 3] = v.w;
            }
            unsigned long long bp[TN / 2];
#pragma unroll
            for (int j = 0; j < TN; j += 4) {
                float4 v = *(const float4*)&Bs[k][tcol * TN + j];
                bp[j / 2] = pack2(v.x, v.y);
                bp[j / 2 + 1] = pack2(v.z, v.w);
            }
#pragma unroll
            for (int i = 0; i < TM; i++) {
                const unsigned long long aa = pack2(a[i], a[i]);
#pragma unroll
                for (int j = 0; j < TN / 2; j++) acc[i][j] = ffma2(aa, bp[j], acc[i][j]);
            }
        }
        __syncthreads();
    }
    // epilogue
#pragma unroll
    for (int i = 0; i < TM; i++) {
        const int r = m0 + trow * TM + i;
        const long orow = ROW_REMAP ? ((long)(r & 255) * NSEQ + (r >> 8)) : (long)r;
#pragma unroll
        for (int j = 0; j < TN / 2; j++) {
            float2 v = unpack2(acc[i][j]);
            const int c = n0 + tcol * TN + j * 2;
            if (biasp) { v.x += biasp[c]; v.y += biasp[c + 1]; }
            if (DO_RELU) { v.x = fmaxf(v.x, 0.f); v.y = fmaxf(v.y, 0.f); }
            *(float2*)(C + orow * ldc + c) = v;
        }
    }
}

// ---------------- preprocessing: build padded vec, padded W_emb, h0, types ---------
__global__ void prep_kernel(const float* __restrict__ inp,
                            const float* __restrict__ st0,
                            const float* __restrict__ Wemb) {
    const long TV = (long)NSEQ * S_ * KVEC;
    const long TW = 5L * KVEC * EMBD;
    const long TH = (long)NSEQ * H_;
    long idx = (long)blockIdx.x * blockDim.x + threadIdx.x;
    if (idx < TV) {
        int f = (int)(idx % KVEC);
        long r = idx / KVEC;
        int s = (int)(r % S_);
        int n = (int)(r / S_);
        int b = n / A_, a = n % A_;
        float v = 0.f;
        if (f < 72)        v = inp[(long)(b * S_ + s) * OBS_ + GLOB_ + a * AGF_ + f + 1];
        else if (f < 102)  v = inp[(long)(b * S_ + s) * OBS_ + (f - 72)];
        g_vec[idx] = v;
    } else if (idx < TV + TW) {
        long i = idx - TV;
        int d = (int)(i % EMBD);
        long r = i / EMBD;
        int k = (int)(r % KVEC);
        int t = (int)(r / KVEC);
        g_wemb[i] = (k < 102) ? Wemb[(long)(t * 102 + k) * EMBD + d] : 0.f;
    } else if (idx < TV + TW + TH) {
        long i = idx - TV - TW;
        g_ha[i] = st0[i];
    } else if (idx < TV + TW + TH + NSEQ) {
        int n = (int)(idx - TV - TW - TH);
        int b = n / A_, a = n % A_;
        g_types[n] = (int)(inp[(long)(b * S_) * OBS_ + GLOB_ + a * AGF_ + 1] + 0.5f);
    }
}

// ---------------- GRU gate elementwise ---------------------------------------------
__global__ void gru_gate_kernel(const float* __restrict__ xg, const float* __restrict__ hg,
                                const float* __restrict__ h, float* __restrict__ hn) {
    int idx = blockIdx.x * blockDim.x + threadIdx.x;   // 0..196607
    int n = idx >> 10, j = idx & 1023;
    long rb = (long)n * G3H;
    float xr = xg[rb + j], xz = xg[rb + 1024 + j], xn = xg[rb + 2048 + j];
    float hr = hg[rb + j], hz = hg[rb + 1024 + j], hnv = hg[rb + 2048 + j];
    float r = 1.f / (1.f + expf(-(xr + hr)));
    float z = 1.f / (1.f + expf(-(xz + hz)));
    float nv = tanhf(xn + r * hnv);
    hn[idx] = (1.f - z) * nv + z * h[idx];
}

// ---------------- fused GAT attention (one block per batch) ------------------------
__global__ void gat_attn_kernel(const float* __restrict__ hf, const float* __restrict__ as_,
                                const float* __restrict__ ad_, float* __restrict__ gout) {
    __shared__ float sh[6 * 1024];
    __shared__ float s_src[4][6], s_dst[4][6], s_att[4][6][6];
    int b = blockIdx.x, tid = threadIdx.x;
    for (int i = tid; i < 6 * 1024; i += 256) sh[i] = hf[(long)b * 6144 + i];
    __syncthreads();
    int lane = tid & 31, w = tid >> 5;
    for (int p = w; p < 24; p += 8) {
        int h = p / 6, n = p % 6;
        float ss = 0.f, dd = 0.f;
        const float* hv = &sh[n * 1024 + h * 256];
        for (int d = lane; d < 256; d += 32) {
            float v = hv[d];
            ss += v * as_[h * 256 + d];
            dd += v * ad_[h * 256 + d];
        }
        for (int o = 16; o > 0; o >>= 1) {
            ss += __shfl_xor_sync(0xffffffffu, ss, o);
            dd += __shfl_xor_sync(0xffffffffu, dd, o);
        }
        if (lane == 0) { s_src[h][n] = ss; s_dst[h][n] = dd; }
    }
    __syncthreads();
    if (tid < 24) {
        int h = tid / 6, i = tid % 6;
        float e[6]; float mx = -1e30f;
#pragma unroll
        for (int j = 0; j < 6; j++) {
            float x = s_src[h][i] + s_dst[h][j];
            x = (x >= 0.f) ? x : 0.2f * x;      // leaky_relu(0.2)
            e[j] = x; mx = fmaxf(mx, x);
        }
        float sum = 0.f;
#pragma unroll
        for (int j = 0; j < 6; j++) { e[j] = expf(e[j] - mx); sum += e[j]; }
        float inv = 1.f / sum;
#pragma unroll
        for (int j = 0; j < 6; j++) s_att[h][i][j] = e[j] * inv;
    }
    __syncthreads();
    for (int o = tid; o < 6 * 1024; o += 256) {
        int i = o >> 10; int hd = o & 1023; int h = hd >> 8;
        float acc = 0.f;
#pragma unroll
        for (int j = 0; j < 6; j++) acc += s_att[h][i][j] * sh[j * 1024 + hd];
        gout[(long)b * 6144 + o] = (acc > 0.f) ? acc : expm1f(acc);   // elu
    }
}

// ---------------- per-type MLP head (one block per batch) --------------------------
__global__ void head_kernel(const float* __restrict__ g1, const float* __restrict__ Wa1,
                            const float* __restrict__ ba1, const float* __restrict__ Wa2,
                            const float* __restrict__ ba2, const int* __restrict__ types,
                            float* __restrict__ logits) {
    __shared__ float f0[1024];
    __shared__ float h1[512];
    int b = blockIdx.x, tid = threadIdx.x;
    int pt = types[b * A_];
    for (int i = tid; i < 1024; i += 256) f0[i] = g1[(long)b * A_ * H_ + i];  // node 0
    __syncthreads();
    for (int d = tid; d < 512; d += 256) {
        const float* W = Wa1 + (long)pt * 1024 * 512 + d;
        float acc = ba1[pt * 512 + d];
#pragma unroll 4
        for (int f = 0; f < 1024; f++) acc += f0[f] * W[(long)f * 512];
        h1[d] = fmaxf(acc, 0.f);
    }
    __syncthreads();
    if (tid < 52) {
        const float* W2 = Wa2 + (long)pt * 512 * 52;
        float acc = ba2[pt * 52 + tid];
#pragma unroll 4
        for (int f = 0; f < 512; f++) acc += h1[f] * W2[f * 52 + tid];
        logits[b * 52 + tid] = acc;
    }
}

// ---------------- final output: masked logits + hT ---------------------------------
__global__ void final_kernel(const float* __restrict__ inp, const float* __restrict__ hT,
                             const float* __restrict__ logits, float* __restrict__ out) {
    int idx = blockIdx.x * blockDim.x + threadIdx.x;
    if (idx < NLOG) {
        int m = idx % MASK_;
        int bs = idx / MASK_;
        float mask = inp[(long)bs * OBS_ + (OBS_ - MASK_) + m];
        int b = bs / S_;
        out[idx] = (mask != 0.f) ? logits[b * MASK_ + m] : 0.f;
    } else if (idx < NLOG + NSEQ * H_) {
        out[idx] = hT[idx - NLOG];
    }
}

// ---------------- launch ------------------------------------------------------------
extern "C" void kernel_launch(void* const* d_in, const int* in_sizes, int n_in,
                              void* d_out, int out_size) {
    const float* inputs = (const float*)d_in[0];
    const float* state0 = (const float*)d_in[1];
    const float* W_emb  = (const float*)d_in[2];
    const float* b_emb  = (const float*)d_in[3];
    const float* W_ih   = (const float*)d_in[4];
    const float* W_hh   = (const float*)d_in[5];
    const float* b_ih   = (const float*)d_in[6];
    const float* b_hh   = (const float*)d_in[7];
    const float* Wg0    = (const float*)d_in[8];
    const float* a0s    = (const float*)d_in[9];
    const float* a0d    = (const float*)d_in[10];
    const float* Wg1    = (const float*)d_in[11];
    const float* a1s    = (const float*)d_in[12];
    const float* a1d    = (const float*)d_in[13];
    const float* Wa1    = (const float*)d_in[14];
    const float* ba1    = (const float*)d_in[15];
    const float* Wa2    = (const float*)d_in[16];
    const float* ba2    = (const float*)d_in[17];
    float* out = (float*)d_out;

    float *vec, *wemb, *emb, *xg, *ha, *hb, *hg, *hf, *g0, *g1, *logits;
    int* types;
    cudaGetSymbolAddress((void**)&vec, g_vec);
    cudaGetSymbolAddress((void**)&wemb, g_wemb);
    cudaGetSymbolAddress((void**)&types, g_types);
    cudaGetSymbolAddress((void**)&emb, g_emb);
    cudaGetSymbolAddress((void**)&xg, g_xg);
    cudaGetSymbolAddress((void**)&ha, g_ha);
    cudaGetSymbolAddress((void**)&hb, g_hb);
    cudaGetSymbolAddress((void**)&hg, g_hg);
    cudaGetSymbolAddress((void**)&hf, g_hf);
    cudaGetSymbolAddress((void**)&g0, g_g0);
    cudaGetSymbolAddress((void**)&g1, g_g1);
    cudaGetSymbolAddress((void**)&logits, g_logits);

    // 1) preprocessing
    {
        long total = (long)NSEQ * S_ * KVEC + 5L * KVEC * EMBD + (long)NSEQ * H_ + NSEQ;
        prep_kernel<<<(unsigned)((total + 255) / 256), 256>>>(inputs, state0, W_emb);
    }
    // 2) emb = relu(vec @ W_emb[type] + b_emb[type])   M=49152,N=512,K=112 (NN, per-type)
    gemm_kernel<64, 128, 4, 8, false, true, false, true>
        <<<dim3(EMBD / 128, MROWS / 64), 256>>>(vec, wemb, b_emb, emb,
            MROWS, EMBD, KVEC, KVEC, EMBD, EMBD, types, (long)KVEC * EMBD, EMBD);
    // 3) xg = emb @ W_ih^T + b_ih -> step-major       M=49152,N=3072,K=512 (NT, remap)
    gemm_kernel<64, 128, 4, 8, true, false, true, false>
        <<<dim3(G3H / 128, MROWS / 64), 256>>>(emb, W_ih, b_ih, xg,
            MROWS, G3H, EMBD, EMBD, EMBD, G3H, nullptr, 0, 0);
    // 4) GRU: 256 sequential steps (hg GEMM + gate kernel)
    float* hbuf[2] = {ha, hb};
    for (int s = 0; s < 256; ++s) {
        gemm_kernel<64, 64, 4, 4, true, false, false, false>
            <<<dim3(G3H / 64, NSEQ / 64), 256>>>(hbuf[s & 1], W_hh, b_hh, hg,
                NSEQ, G3H, H_, H_, H_, G3H, nullptr, 0, 0);
        gru_gate_kernel<<<NSEQ * H_ / 256, 256>>>(xg + (size_t)s * NSEQ * G3H, hg,
                                                  hbuf[s & 1], hbuf[(s + 1) & 1]);
    }
    float* hT = ha;  // after 256 steps state is back in buffer 0
    // 5) GAT layer 0
    gemm_kernel<64, 64, 4, 4, false, false, false, false>
        <<<dim3(H_ / 64, NSEQ / 64), 256>>>(hT, Wg0, nullptr, hf,
            NSEQ, H_, H_, H_, H_, H_, nullptr, 0, 0);
    gat_attn_kernel<<<B_, 256>>>(hf, a0s, a0d, g0);
    // 6) GAT layer 1
    gemm_kernel<64, 64, 4, 4, false, false, false, false>
        <<<dim3(H_ / 64, NSEQ / 64), 256>>>(g0, Wg1, nullptr, hf,
            NSEQ, H_, H_, H_, H_, H_, nullptr, 0, 0);
    gat_attn_kernel<<<B_, 256>>>(hf, a1s, a1d, g1);
    // 7) head
    head_kernel<<<B_, 256>>>(g1, Wa1, ba1, Wa2, ba2, types, logits);
    // 8) output assembly
    {
        int total = NLOG + NSEQ * H_;
        final_kernel<<<(total + 255) / 256, 256>>>(inputs, hT, logits, out);
    }
}

// round 14
// speedup vs baseline: 1.0006x; 1.0006x over previous
#include <cuda_runtime.h>
#include <math.h>
#include <stdint.h>

#define B_    32
#define S_    256
#define A_    6
#define H_    1024
#define OBS_  520
#define GLOB_ 30
#define MASK_ 52
#define AGF_  73
#define NSEQ  192          // B_*A_
#define KVEC  112          // 102 padded to mult of 16
#define EMBD  512
#define G3H   3072
#define MROWS 49152        // NSEQ*S_
#define NLOG  (B_*S_*MASK_)  // 425984

// ---------------- scratch (device globals; no allocations allowed) ----------------
__device__ float g_vec[(size_t)NSEQ * S_ * KVEC];
__device__ float g_wemb[5 * KVEC * EMBD];
__device__ int   g_types[NSEQ];
__device__ float g_emb[(size_t)MROWS * EMBD];
__device__ float g_xg[(size_t)MROWS * G3H];        // step-major: [s][n][3072]
__device__ float g_ha[NSEQ * H_];
__device__ float g_hb[NSEQ * H_];
__device__ float g_hg[NSEQ * G3H];
__device__ float g_hf[NSEQ * H_];
__device__ float g_g0[NSEQ * H_];
__device__ float g_g1[NSEQ * H_];
__device__ float g_logits[B_ * MASK_];

// ---------------- packed f32x2 helpers (FFMA2: 2x fp32 throughput on sm_103a) ------
__device__ __forceinline__ unsigned long long ffma2(unsigned long long a,
                                                    unsigned long long b,
                                                    unsigned long long c) {
    unsigned long long d;
    asm("fma.rn.f32x2 %0, %1, %2, %3;" : "=l"(d) : "l"(a), "l"(b), "l"(c));
    return d;
}
__device__ __forceinline__ unsigned long long pack2(float x, float y) {
    unsigned long long r;
    asm("mov.b64 %0, {%1, %2};" : "=l"(r) : "f"(x), "f"(y));
    return r;
}
__device__ __forceinline__ float2 unpack2(unsigned long long p) {
    float2 v;
    asm("mov.b64 {%0, %1}, %2;" : "=f"(v.x), "=f"(v.y) : "l"(p));
    return v;
}

// ---------------- generic tiled GEMM: C = A(MxK) * B + bias (opt relu) -------------
// BNT=true : B is (N,K) row-major (C = A * B^T)
// BNT=false: B is (K,N) row-major (C = A * B)
// ROW_REMAP: output row r -> (r%256)*NSEQ + r/256   (n-major -> step-major for xg)
// PER_TYPE : B/bias base advanced by types[m0/256] (embedding GEMM)
template <int BM, int BN, int TM, int TN, bool BNT, bool DO_RELU, bool ROW_REMAP, bool PER_TYPE>
__global__ void __launch_bounds__(256, 2)
gemm_kernel(const float* __restrict__ A, const float* __restrict__ Bm,
            const float* __restrict__ bias, float* __restrict__ C,
            int M, int N, int K, int lda, int ldb, int ldc,
            const int* __restrict__ types, long btstride, int biastride) {
    __shared__ __align__(16) float As[16][BM + 4];
    __shared__ __align__(16) float Bs[16][BN + 4];
    const int tid = threadIdx.x;
    const int m0 = blockIdx.y * BM;
    const int n0 = blockIdx.x * BN;

    const float* Bp = Bm;
    const float* biasp = bias;
    if (PER_TYPE) {
        int t = types[m0 >> 8];
        Bp += (long)t * btstride;
        biasp += (long)t * biastride;
    }

    const int TC = BN / TN;
    const int trow = tid / TC;
    const int tcol = tid % TC;

    unsigned long long acc[TM][TN / 2];
#pragma unroll
    for (int i = 0; i < TM; i++)
#pragma unroll
        for (int j = 0; j < TN / 2; j++) acc[i][j] = 0ULL;

    const int ktiles = K >> 4;
    for (int kt = 0; kt < ktiles; ++kt) {
        const int k0 = kt << 4;
        // load A tile (BM x 16), stored k-major
#pragma unroll
        for (int it = 0; it < (BM * 4) / 256; ++it) {
            int idx = tid + it * 256;
            int row = idx >> 2, kq = idx & 3;
            const float4 v = *(const float4*)(A + (long)(m0 + row) * lda + k0 + kq * 4);
            As[kq * 4 + 0][row] = v.x; As[kq * 4 + 1][row] = v.y;
            As[kq * 4 + 2][row] = v.z; As[kq * 4 + 3][row] = v.w;
        }
        if (BNT) {
#pragma unroll
            for (int it = 0; it < (BN * 4) / 256; ++it) {
                int idx = tid + it * 256;
                int row = idx >> 2, kq = idx & 3;
                const float4 v = *(const float4*)(Bp + (long)(n0 + row) * ldb + k0 + kq * 4);
                Bs[kq * 4 + 0][row] = v.x; Bs[kq * 4 + 1][row] = v.y;
                Bs[kq * 4 + 2][row] = v.z; Bs[kq * 4 + 3][row] = v.w;
            }
        } else {
#pragma unroll
            for (int it = 0; it < (BN * 4) / 256; ++it) {
                int idx = tid + it * 256;
                int kr = idx / (BN / 4), nq = idx % (BN / 4);
                *(float4*)&Bs[kr][nq * 4] =
                    *(const float4*)(Bp + (long)(k0 + kr) * ldb + n0 + nq * 4);
            }
        }
        __syncthreads();
#pragma unroll
        for (int k = 0; k < 16; k++) {
            float a[TM];
#pragma unroll
            for (int i = 0; i < TM; i += 4) {
                float4 v = *(const float4*)&As[k][trow * TM + i];
                a[i] = v.x; a[i + 1] = v.y; a[i + 2] = v.z; a[i + 3] = v.w;
            }
            unsigned long long bp[TN / 2];
#pragma unroll
            for (int j = 0; j < TN; j += 4) {
                float4 v = *(const float4*)&Bs[k][tcol * TN + j];
                bp[j / 2] = pack2(v.x, v.y);
                bp[j / 2 + 1] = pack2(v.z, v.w);
            }
#pragma unroll
            for (int i = 0; i < TM; i++) {
                const unsigned long long aa = pack2(a[i], a[i]);
#pragma unroll
                for (int j = 0; j < TN / 2; j++) acc[i][j] = ffma2(aa, bp[j], acc[i][j]);
            }
        }
        __syncthreads();
    }
    // epilogue
#pragma unroll
    for (int i = 0; i < TM; i++) {
        const int r = m0 + trow * TM + i;
        const long orow = ROW_REMAP ? ((long)(r & 255) * NSEQ + (r >> 8)) : (long)r;
#pragma unroll
        for (int j = 0; j < TN / 2; j++) {
            float2 v = unpack2(acc[i][j]);
            const int c = n0 + tcol * TN + j * 2;
            if (biasp) { v.x += biasp[c]; v.y += biasp[c + 1]; }
            if (DO_RELU) { v.x = fmaxf(v.x, 0.f); v.y = fmaxf(v.y, 0.f); }
            *(float2*)(C + orow * ldc + c) = v;
        }
    }
}

// ---------------- preprocessing: build padded vec, padded W_emb, h0, types ---------
__global__ void prep_kernel(const float* __restrict__ inp,
                            const float* __restrict__ st0,
                            const float* __restrict__ Wemb) {
    const long TV = (long)NSEQ * S_ * KVEC;
    const long TW = 5L * KVEC * EMBD;
    const long TH = (long)NSEQ * H_;
    long idx = (long)blockIdx.x * blockDim.x + threadIdx.x;
    if (idx < TV) {
        int f = (int)(idx % KVEC);
        long r = idx / KVEC;
        int s = (int)(r % S_);
        int n = (int)(r / S_);
        int b = n / A_, a = n % A_;
        float v = 0.f;
        if (f < 72)        v = inp[(long)(b * S_ + s) * OBS_ + GLOB_ + a * AGF_ + f + 1];
        else if (f < 102)  v = inp[(long)(b * S_ + s) * OBS_ + (f - 72)];
        g_vec[idx] = v;
    } else if (idx < TV + TW) {
        long i = idx - TV;
        int d = (int)(i % EMBD);
        long r = i / EMBD;
        int k = (int)(r % KVEC);
        int t = (int)(r / KVEC);
        g_wemb[i] = (k < 102) ? Wemb[(long)(t * 102 + k) * EMBD + d] : 0.f;
    } else if (idx < TV + TW + TH) {
        long i = idx - TV - TW;
        g_ha[i] = st0[i];
    } else if (idx < TV + TW + TH + NSEQ) {
        int n = (int)(idx - TV - TW - TH);
        int b = n / A_, a = n % A_;
        g_types[n] = (int)(inp[(long)(b * S_) * OBS_ + GLOB_ + a * AGF_ + 1] + 0.5f);
    }
}

// ---------------- GRU gate elementwise ---------------------------------------------
__global__ void gru_gate_kernel(const float* __restrict__ xg, const float* __restrict__ hg,
                                const float* __restrict__ h, float* __restrict__ hn) {
    int idx = blockIdx.x * blockDim.x + threadIdx.x;   // 0..196607
    int n = idx >> 10, j = idx & 1023;
    long rb = (long)n * G3H;
    float xr = xg[rb + j], xz = xg[rb + 1024 + j], xn = xg[rb + 2048 + j];
    float hr = hg[rb + j], hz = hg[rb + 1024 + j], hnv = hg[rb + 2048 + j];
    float r = 1.f / (1.f + expf(-(xr + hr)));
    float z = 1.f / (1.f + expf(-(xz + hz)));
    float nv = tanhf(xn + r * hnv);
    hn[idx] = (1.f - z) * nv + z * h[idx];
}

// ---------------- fused GAT attention (one block per batch) ------------------------
__global__ void gat_attn_kernel(const float* __restrict__ hf, const float* __restrict__ as_,
                                const float* __restrict__ ad_, float* __restrict__ gout) {
    __shared__ float sh[6 * 1024];
    __shared__ float s_src[4][6], s_dst[4][6], s_att[4][6][6];
    int b = blockIdx.x, tid = threadIdx.x;
    for (int i = tid; i < 6 * 1024; i += 256) sh[i] = hf[(long)b * 6144 + i];
    __syncthreads();
    int lane = tid & 31, w = tid >> 5;
    for (int p = w; p < 24; p += 8) {
        int h = p / 6, n = p % 6;
        float ss = 0.f, dd = 0.f;
        const float* hv = &sh[n * 1024 + h * 256];
        for (int d = lane; d < 256; d += 32) {
            float v = hv[d];
            ss += v * as_[h * 256 + d];
            dd += v * ad_[h * 256 + d];
        }
        for (int o = 16; o > 0; o >>= 1) {
            ss += __shfl_xor_sync(0xffffffffu, ss, o);
            dd += __shfl_xor_sync(0xffffffffu, dd, o);
        }
        if (lane == 0) { s_src[h][n] = ss; s_dst[h][n] = dd; }
    }
    __syncthreads();
    if (tid < 24) {
        int h = tid / 6, i = tid % 6;
        float e[6]; float mx = -1e30f;
#pragma unroll
        for (int j = 0; j < 6; j++) {
            float x = s_src[h][i] + s_dst[h][j];
            x = (x >= 0.f) ? x : 0.2f * x;      // leaky_relu(0.2)
            e[j] = x; mx = fmaxf(mx, x);
        }
        float sum = 0.f;
#pragma unroll
        for (int j = 0; j < 6; j++) { e[j] = expf(e[j] - mx); sum += e[j]; }
        float inv = 1.f / sum;
#pragma unroll
        for (int j = 0; j < 6; j++) s_att[h][i][j] = e[j] * inv;
    }
    __syncthreads();
    for (int o = tid; o < 6 * 1024; o += 256) {
        int i = o >> 10; int hd = o & 1023; int h = hd >> 8;
        float acc = 0.f;
#pragma unroll
        for (int j = 0; j < 6; j++) acc += s_att[h][i][j] * sh[j * 1024 + hd];
        gout[(long)b * 6144 + o] = (acc > 0.f) ? acc : expm1f(acc);   // elu
    }
}

// ---------------- per-type MLP head (one block per batch) --------------------------
__global__ void head_kernel(const float* __restrict__ g1, const float* __restrict__ Wa1,
                            const float* __restrict__ ba1, const float* __restrict__ Wa2,
                            const float* __restrict__ ba2, const int* __restrict__ types,
                            float* __restrict__ logits) {
    __shared__ float f0[1024];
    __shared__ float h1[512];
    int b = blockIdx.x, tid = threadIdx.x;
    int pt = types[b * A_];
    for (int i = tid; i < 1024; i += 256) f0[i] = g1[(long)b * A_ * H_ + i];  // node 0
    __syncthreads();
    for (int d = tid; d < 512; d += 256) {
        const float* W = Wa1 + (long)pt * 1024 * 512 + d;
        float acc = ba1[pt * 512 + d];
#pragma unroll 4
        for (int f = 0; f < 1024; f++) acc += f0[f] * W[(long)f * 512];
        h1[d] = fmaxf(acc, 0.f);
    }
    __syncthreads();
    if (tid < 52) {
        const float* W2 = Wa2 + (long)pt * 512 * 52;
        float acc = ba2[pt * 52 + tid];
#pragma unroll 4
        for (int f = 0; f < 512; f++) acc += h1[f] * W2[f * 52 + tid];
        logits[b * 52 + tid] = acc;
    }
}

// ---------------- final output: masked logits + hT ---------------------------------
__global__ void final_kernel(const float* __restrict__ inp, const float* __restrict__ hT,
                             const float* __restrict__ logits, float* __restrict__ out) {
    int idx = blockIdx.x * blockDim.x + threadIdx.x;
    if (idx < NLOG) {
        int m = idx % MASK_;
        int bs = idx / MASK_;
        float mask = inp[(long)bs * OBS_ + (OBS_ - MASK_) + m];
        int b = bs / S_;
        out[idx] = (mask != 0.f) ? logits[b * MASK_ + m] : 0.f;
    } else if (idx < NLOG + NSEQ * H_) {
        out[idx] = hT[idx - NLOG];
    }
}

// ---------------- launch ------------------------------------------------------------
extern "C" void kernel_launch(void* const* d_in, const int* in_sizes, int n_in,
                              void* d_out, int out_size) {
    const float* inputs = (const float*)d_in[0];
    const float* state0 = (const float*)d_in[1];
    const float* W_emb  = (const float*)d_in[2];
    const float* b_emb  = (const float*)d_in[3];
    const float* W_ih   = (const float*)d_in[4];
    const float* W_hh   = (const float*)d_in[5];
    const float* b_ih   = (const float*)d_in[6];
    const float* b_hh   = (const float*)d_in[7];
    const float* Wg0    = (const float*)d_in[8];
    const float* a0s    = (const float*)d_in[9];
    const float* a0d    = (const float*)d_in[10];
    const float* Wg1    = (const float*)d_in[11];
    const float* a1s    = (const float*)d_in[12];
    const float* a1d    = (const float*)d_in[13];
    const float* Wa1    = (const float*)d_in[14];
    const float* ba1    = (const float*)d_in[15];
    const float* Wa2    = (const float*)d_in[16];
    const float* ba2    = (const float*)d_in[17];
    float* out = (float*)d_out;

    float *vec, *wemb, *emb, *xg, *ha, *hb, *hg, *hf, *g0, *g1, *logits;
    int* types;
    cudaGetSymbolAddress((void**)&vec, g_vec);
    cudaGetSymbolAddress((void**)&wemb, g_wemb);
    cudaGetSymbolAddress((void**)&types, g_types);
    cudaGetSymbolAddress((void**)&emb, g_emb);
    cudaGetSymbolAddress((void**)&xg, g_xg);
    cudaGetSymbolAddress((void**)&ha, g_ha);
    cudaGetSymbolAddress((void**)&hb, g_hb);
    cudaGetSymbolAddress((void**)&hg, g_hg);
    cudaGetSymbolAddress((void**)&hf, g_hf);
    cudaGetSymbolAddress((void**)&g0, g_g0);
    cudaGetSymbolAddress((void**)&g1, g_g1);
    cudaGetSymbolAddress((void**)&logits, g_logits);

    // 1) preprocessing
    {
        long total = (long)NSEQ * S_ * KVEC + 5L * KVEC * EMBD + (long)NSEQ * H_ + NSEQ;
        prep_kernel<<<(unsigned)((total + 255) / 256), 256>>>(inputs, state0, W_emb);
    }
    // 2) emb = relu(vec @ W_emb[type] + b_emb[type])   M=49152,N=512,K=112 (NN, per-type)
    gemm_kernel<64, 128, 4, 8, false, true, false, true>
        <<<dim3(EMBD / 128, MROWS / 64), 256>>>(vec, wemb, b_emb, emb,
            MROWS, EMBD, KVEC, KVEC, EMBD, EMBD, types, (long)KVEC * EMBD, EMBD);
    // 3) xg = emb @ W_ih^T + b_ih -> step-major       M=49152,N=3072,K=512 (NT, remap)
    gemm_kernel<64, 128, 4, 8, true, false, true, false>
        <<<dim3(G3H / 128, MROWS / 64), 256>>>(emb, W_ih, b_ih, xg,
            MROWS, G3H, EMBD, EMBD, EMBD, G3H, nullptr, 0, 0);
    // 4) GRU: 256 sequential steps (hg GEMM + gate kernel)
    float* hbuf[2] = {ha, hb};
    for (int s = 0; s < 256; ++s) {
        gemm_kernel<64, 64, 4, 4, true, false, false, false>
            <<<dim3(G3H / 64, NSEQ / 64), 256>>>(hbuf[s & 1], W_hh, b_hh, hg,
                NSEQ, G3H, H_, H_, H_, G3H, nullptr, 0, 0);
        gru_gate_kernel<<<NSEQ * H_ / 256, 256>>>(xg + (size_t)s * NSEQ * G3H, hg,
                                                  hbuf[s & 1], hbuf[(s + 1) & 1]);
    }
    float* hT = ha;  // after 256 steps state is back in buffer 0
    // 5) GAT layer 0
    gemm_kernel<64, 64, 4, 4, false, false, false, false>
        <<<dim3(H_ / 64, NSEQ / 64), 256>>>(hT, Wg0, nullptr, hf,
            NSEQ, H_, H_, H_, H_, H_, nullptr, 0, 0);
    gat_attn_kernel<<<B_, 256>>>(hf, a0s, a0d, g0);
    // 6) GAT layer 1
    gemm_kernel<64, 64, 4, 4, false, false, false, false>
        <<<dim3(H_ / 64, NSEQ / 64), 256>>>(g0, Wg1, nullptr, hf,
            NSEQ, H_, H_, H_, H_, H_, nullptr, 0, 0);
    gat_attn_kernel<<<B_, 256>>>(hf, a1s, a1d, g1);
    // 7) head
    head_kernel<<<B_, 256>>>(g1, Wa1, ba1, Wa2, ba2, types, logits);
    // 8) output assembly
    {
        int total = NLOG + NSEQ * H_;
        final_kernel<<<(total + 255) / 256, 256>>>(inputs, hT, logits, out);
    }
}

// round 15
// speedup vs baseline: 1.2756x; 1.2748x over previous
#include <cuda_runtime.h>
#include <math.h>
#include <stdint.h>

#define B_    32
#define S_    256
#define A_    6
#define H_    1024
#define OBS_  520
#define GLOB_ 30
#define MASK_ 52
#define AGF_  73
#define NSEQ  192          // B_*A_
#define KVEC  112          // 102 padded to mult of 16
#define EMBD  512
#define G3H   3072
#define MROWS 49152        // NSEQ*S_
#define NLOG  (B_*S_*MASK_)  // 425984
#define NBLK  128          // persistent GRU grid (4 row-groups x 32 col-groups)

// ---------------- scratch (device globals; no allocations allowed) ----------------
__device__ float g_vec[(size_t)NSEQ * S_ * KVEC];
__device__ float g_wemb[5 * KVEC * EMBD];
__device__ int   g_types[NSEQ];
__device__ float g_emb[(size_t)MROWS * EMBD];
__device__ float g_xg[(size_t)MROWS * G3H];        // step-major: [s][n][3072]
__device__ float g_ha[NSEQ * H_];
__device__ float g_hb[NSEQ * H_];
__device__ float g_hf[NSEQ * H_];
__device__ float g_g0[NSEQ * H_];
__device__ float g_g1[NSEQ * H_];
__device__ float g_logits[B_ * MASK_];
__device__ __align__(16) float g_wp[(size_t)32 * 96 * H_];  // W_hh permuted per col-group
__device__ unsigned g_bar;

// ---------------- packed f32x2 helpers (FFMA2: 2x fp32 throughput on sm_103a) ------
__device__ __forceinline__ unsigned long long ffma2(unsigned long long a,
                                                    unsigned long long b,
                                                    unsigned long long c) {
    unsigned long long d;
    asm("fma.rn.f32x2 %0, %1, %2, %3;" : "=l"(d) : "l"(a), "l"(b), "l"(c));
    return d;
}
__device__ __forceinline__ unsigned long long pack2(float x, float y) {
    unsigned long long r;
    asm("mov.b64 %0, {%1, %2};" : "=l"(r) : "f"(x), "f"(y));
    return r;
}
__device__ __forceinline__ float2 unpack2(unsigned long long p) {
    float2 v;
    asm("mov.b64 {%0, %1}, %2;" : "=f"(v.x), "=f"(v.y) : "l"(p));
    return v;
}

// ---------------- generic tiled GEMM (unchanged; used for emb/xg/GAT projections) --
template <int BM, int BN, int TM, int TN, bool BNT, bool DO_RELU, bool ROW_REMAP, bool PER_TYPE>
__global__ void __launch_bounds__(256, 2)
gemm_kernel(const float* __restrict__ A, const float* __restrict__ Bm,
            const float* __restrict__ bias, float* __restrict__ C,
            int M, int N, int K, int lda, int ldb, int ldc,
            const int* __restrict__ types, long btstride, int biastride) {
    __shared__ __align__(16) float As[16][BM + 4];
    __shared__ __align__(16) float Bs[16][BN + 4];
    const int tid = threadIdx.x;
    const int m0 = blockIdx.y * BM;
    const int n0 = blockIdx.x * BN;

    const float* Bp = Bm;
    const float* biasp = bias;
    if (PER_TYPE) {
        int t = types[m0 >> 8];
        Bp += (long)t * btstride;
        biasp += (long)t * biastride;
    }

    const int TC = BN / TN;
    const int trow = tid / TC;
    const int tcol = tid % TC;

    unsigned long long acc[TM][TN / 2];
#pragma unroll
    for (int i = 0; i < TM; i++)
#pragma unroll
        for (int j = 0; j < TN / 2; j++) acc[i][j] = 0ULL;

    const int ktiles = K >> 4;
    for (int kt = 0; kt < ktiles; ++kt) {
        const int k0 = kt << 4;
#pragma unroll
        for (int it = 0; it < (BM * 4) / 256; ++it) {
            int idx = tid + it * 256;
            int row = idx >> 2, kq = idx & 3;
            const float4 v = *(const float4*)(A + (long)(m0 + row) * lda + k0 + kq * 4);
            As[kq * 4 + 0][row] = v.x; As[kq * 4 + 1][row] = v.y;
            As[kq * 4 + 2][row] = v.z; As[kq * 4 + 3][row] = v.w;
        }
        if (BNT) {
#pragma unroll
            for (int it = 0; it < (BN * 4) / 256; ++it) {
                int idx = tid + it * 256;
                int row = idx >> 2, kq = idx & 3;
                const float4 v = *(const float4*)(Bp + (long)(n0 + row) * ldb + k0 + kq * 4);
                Bs[kq * 4 + 0][row] = v.x; Bs[kq * 4 + 1][row] = v.y;
                Bs[kq * 4 + 2][row] = v.z; Bs[kq * 4 + 3][row] = v.w;
            }
        } else {
#pragma unroll
            for (int it = 0; it < (BN * 4) / 256; ++it) {
                int idx = tid + it * 256;
                int kr = idx / (BN / 4), nq = idx % (BN / 4);
                *(float4*)&Bs[kr][nq * 4] =
                    *(const float4*)(Bp + (long)(k0 + kr) * ldb + n0 + nq * 4);
            }
        }
        __syncthreads();
#pragma unroll
        for (int k = 0; k < 16; k++) {
            float a[TM];
#pragma unroll
            for (int i = 0; i < TM; i += 4) {
                float4 v = *(const float4*)&As[k][trow * TM + i];
                a[i] = v.x; a[i + 1] = v.y; a[i + 2] = v.z; a[i + 3] = v.w;
            }
            unsigned long long bp[TN / 2];
#pragma unroll
            for (int j = 0; j < TN; j += 4) {
                float4 v = *(const float4*)&Bs[k][tcol * TN + j];
                bp[j / 2] = pack2(v.x, v.y);
                bp[j / 2 + 1] = pack2(v.z, v.w);
            }
#pragma unroll
            for (int i = 0; i < TM; i++) {
                const unsigned long long aa = pack2(a[i], a[i]);
#pragma unroll
                for (int j = 0; j < TN / 2; j++) acc[i][j] = ffma2(aa, bp[j], acc[i][j]);
            }
        }
        __syncthreads();
    }
#pragma unroll
    for (int i = 0; i < TM; i++) {
        const int r = m0 + trow * TM + i;
        const long orow = ROW_REMAP ? ((long)(r & 255) * NSEQ + (r >> 8)) : (long)r;
#pragma unroll
        for (int j = 0; j < TN / 2; j++) {
            float2 v = unpack2(acc[i][j]);
            const int c = n0 + tcol * TN + j * 2;
            if (biasp) { v.x += biasp[c]; v.y += biasp[c + 1]; }
            if (DO_RELU) { v.x = fmaxf(v.x, 0.f); v.y = fmaxf(v.y, 0.f); }
            *(float2*)(C + orow * ldc + c) = v;
        }
    }
}

// ---------------- preprocessing: vec, W_emb pad, h0, types, W_hh permute, barrier --
__global__ void prep_kernel(const float* __restrict__ inp,
                            const float* __restrict__ st0,
                            const float* __restrict__ Wemb,
                            const float* __restrict__ Whh) {
    const long TV = (long)NSEQ * S_ * KVEC;
    const long TW = 5L * KVEC * EMBD;
    const long TH = (long)NSEQ * H_;
    const long TP = 3L * H_ * H_;      // permuted W_hh elements
    long idx = (long)blockIdx.x * blockDim.x + threadIdx.x;
    if (idx < TV) {
        int f = (int)(idx % KVEC);
        long r = idx / KVEC;
        int s = (int)(r % S_);
        int n = (int)(r / S_);
        int b = n / A_, a = n % A_;
        float v = 0.f;
        if (f < 72)        v = inp[(long)(b * S_ + s) * OBS_ + GLOB_ + a * AGF_ + f + 1];
        else if (f < 102)  v = inp[(long)(b * S_ + s) * OBS_ + (f - 72)];
        g_vec[idx] = v;
    } else if (idx < TV + TW) {
        long i = idx - TV;
        int d = (int)(i % EMBD);
        long r = i / EMBD;
        int k = (int)(r % KVEC);
        int t = (int)(r / KVEC);
        g_wemb[i] = (k < 102) ? Wemb[(long)(t * 102 + k) * EMBD + d] : 0.f;
    } else if (idx < TV + TW + TH) {
        long i = idx - TV - TW;
        g_ha[i] = st0[i];
    } else if (idx < TV + TW + TH + NSEQ) {
        int n = (int)(idx - TV - TW - TH);
        int b = n / A_, a = n % A_;
        g_types[n] = (int)(inp[(long)(b * S_) * OBS_ + GLOB_ + a * AGF_ + 1] + 0.5f);
    } else if (idx < TV + TW + TH + NSEQ + TP) {
        long p = idx - (TV + TW + TH + NSEQ);
        int k = (int)(p & 1023);
        long wr = p >> 10;               // cg*96 + local row
        int cgi = (int)(wr / 96);
        int r = (int)(wr % 96);
        int g = r >> 5, i = r & 31;      // gate (r/z/n), j within col-group
        g_wp[p] = Whh[((size_t)(g * H_ + cgi * 32 + i)) * H_ + k];
    } else if (idx == TV + TW + TH + NSEQ + TP) {
        g_bar = 0u;
    }
}

// ---------------- persistent fused GRU: 256 steps, GEMM + gates + grid barrier -----
// grid = 128 blocks (all co-resident): rg = blk/32 (48 rows), cg = blk%32 (32 h-cols)
// Block computes hg tile 48x96 (cols = gates r/z/n for its 32 j's) with k-paired
// FFMA2 (acc.lo = even k, acc.hi = odd k), then fused gate update, then grid barrier.
__global__ void __launch_bounds__(256, 1)
gru_persistent(const float* __restrict__ xg, const float* __restrict__ bhh,
               float* __restrict__ hA, float* __restrict__ hB) {
    __shared__ unsigned long long As2[48 * 34];   // [row*34 + kpair], kpair in [0,32)
    __shared__ unsigned long long Bs2[96 * 34];
    float* Cs = (float*)Bs2;                      // reused after last tile (48*97 floats)

    const int tid = threadIdx.x;
    const int blk = blockIdx.x;
    const int rg = blk >> 5;
    const int cg = blk & 31;
    const int r0 = rg * 48;
    const float* wbase = g_wp + (size_t)cg * 96 * H_;

    const int w = tid >> 5;
    const int lane = tid & 31;
    const int warpR = w >> 2, warpC = w & 3;      // warps 2x4, warp tile 24x24
    const int ly = lane >> 3, lx = lane & 7;      // lanes 4x8, lane tile 6x3
    const int rowbase = warpR * 24 + ly * 6;
    const int colbase = warpC * 24 + lx * 3;

    // hoisted biases for this thread's 6 gate cells (fixed across steps)
    float br[6], bz[6], bn[6];
#pragma unroll
    for (int c = 0; c < 6; c++) {
        int idx = tid + c * 256;
        int jg = cg * 32 + (idx & 31);
        br[c] = bhh[jg];
        bz[c] = bhh[1024 + jg];
        bn[c] = bhh[2048 + jg];
    }

    for (int s = 0; s < 256; ++s) {
        const float* hin = (s & 1) ? hB : hA;
        float* hout      = (s & 1) ? hA : hB;
        const float* xgs = xg + (size_t)s * (NSEQ * G3H);

        unsigned long long acc[6][3];
#pragma unroll
        for (int i = 0; i < 6; i++)
#pragma unroll
            for (int j = 0; j < 3; j++) acc[i][j] = 0ULL;

        float4 pa[3], pb[6];
        // prologue: load k-tile 0
#pragma unroll
        for (int i = 0; i < 3; i++) {
            int p = tid + i * 256; int row = p >> 4; int f4 = p & 15;
            pa[i] = __ldcg((const float4*)(hin + (size_t)(r0 + row) * H_) + f4);
        }
#pragma unroll
        for (int i = 0; i < 6; i++) {
            int p = tid + i * 256; int row = p >> 4; int f4 = p & 15;
            pb[i] = __ldg((const float4*)(wbase + (size_t)row * H_) + f4);
        }
#pragma unroll
        for (int i = 0; i < 3; i++) {
            int p = tid + i * 256; int row = p >> 4; int f4 = p & 15;
            *(float4*)&As2[row * 34 + f4 * 2] = pa[i];
        }
#pragma unroll
        for (int i = 0; i < 6; i++) {
            int p = tid + i * 256; int row = p >> 4; int f4 = p & 15;
            *(float4*)&Bs2[row * 34 + f4 * 2] = pb[i];
        }
        __syncthreads();

        for (int kt = 0; kt < 16; ++kt) {
            if (kt < 15) {
                const int base4 = (kt + 1) << 4;     // k-tile offset in float4 units
#pragma unroll
                for (int i = 0; i < 3; i++) {
                    int p = tid + i * 256; int row = p >> 4; int f4 = p & 15;
                    pa[i] = __ldcg((const float4*)(hin + (size_t)(r0 + row) * H_) + base4 + f4);
                }
#pragma unroll
                for (int i = 0; i < 6; i++) {
                    int p = tid + i * 256; int row = p >> 4; int f4 = p & 15;
                    pb[i] = __ldg((const float4*)(wbase + (size_t)row * H_) + base4 + f4);
                }
            }
            // compute: 16 k-quads (64 k) from smem, k-paired ffma2
#pragma unroll 8
            for (int kq = 0; kq < 16; kq++) {
                ulonglong2 av[6], bv[3];
#pragma unroll
                for (int i = 0; i < 6; i++)
                    av[i] = *(const ulonglong2*)&As2[(rowbase + i) * 34 + kq * 2];
#pragma unroll
                for (int j = 0; j < 3; j++)
                    bv[j] = *(const ulonglong2*)&Bs2[(colbase + j) * 34 + kq * 2];
#pragma unroll
                for (int i = 0; i < 6; i++)
#pragma unroll
                    for (int j = 0; j < 3; j++) {
                        acc[i][j] = ffma2(av[i].x, bv[j].x, acc[i][j]);
                        acc[i][j] = ffma2(av[i].y, bv[j].y, acc[i][j]);
                    }
            }
            __syncthreads();
            if (kt < 15) {
#pragma unroll
                for (int i = 0; i < 3; i++) {
                    int p = tid + i * 256; int row = p >> 4; int f4 = p & 15;
                    *(float4*)&As2[row * 34 + f4 * 2] = pa[i];
                }
#pragma unroll
                for (int i = 0; i < 6; i++) {
                    int p = tid + i * 256; int row = p >> 4; int f4 = p & 15;
                    *(float4*)&Bs2[row * 34 + f4 * 2] = pb[i];
                }
                __syncthreads();
            }
        }

        // C tile -> smem (horizontal add of k-paired halves)
#pragma unroll
        for (int i = 0; i < 6; i++)
#pragma unroll
            for (int j = 0; j < 3; j++) {
                float2 v = unpack2(acc[i][j]);
                Cs[(rowbase + i) * 97 + colbase + j] = v.x + v.y;
            }
        __syncthreads();

        // fused gates: 48x32 cells, 6 per thread
        float xr[6], xz[6], xn[6], hold[6], hr[6], hz[6], hn[6];
#pragma unroll
        for (int c = 0; c < 6; c++) {
            int idx = tid + c * 256;
            int row = idx >> 5, jl = idx & 31;
            int jg = cg * 32 + jl;
            int grow = r0 + row;
            const float* xb = xgs + (size_t)grow * G3H + jg;
            xr[c] = __ldg(xb);
            xz[c] = __ldg(xb + 1024);
            xn[c] = __ldg(xb + 2048);
            hold[c] = __ldcg(hin + (size_t)grow * H_ + jg);
            hr[c] = Cs[row * 97 + jl] + br[c];
            hz[c] = Cs[row * 97 + 32 + jl] + bz[c];
            hn[c] = Cs[row * 97 + 64 + jl] + bn[c];
        }
#pragma unroll
        for (int c = 0; c < 6; c++) {
            int idx = tid + c * 256;
            int row = idx >> 5, jl = idx & 31;
            int jg = cg * 32 + jl;
            int grow = r0 + row;
            float r = 1.f / (1.f + expf(-(xr[c] + hr[c])));
            float z = 1.f / (1.f + expf(-(xz[c] + hz[c])));
            float nv = tanhf(xn[c] + r * hn[c]);
            __stcg(hout + (size_t)grow * H_ + jg, (1.f - z) * nv + z * hold[c]);
        }

        // grid-wide barrier (all 128 blocks co-resident)
        if (s < 255) {
            __syncthreads();
            if (tid == 0) {
                __threadfence();
                atomicAdd(&g_bar, 1u);
                const unsigned target = (unsigned)(s + 1) * NBLK;
                volatile unsigned* vb = &g_bar;
                while (*vb < target) {}
                __threadfence();
            }
            __syncthreads();
        }
    }
}

// ---------------- fused GAT attention (one block per batch) ------------------------
__global__ void gat_attn_kernel(const float* __restrict__ hf, const float* __restrict__ as_,
                                const float* __restrict__ ad_, float* __restrict__ gout) {
    __shared__ float sh[6 * 1024];
    __shared__ float s_src[4][6], s_dst[4][6], s_att[4][6][6];
    int b = blockIdx.x, tid = threadIdx.x;
    for (int i = tid; i < 6 * 1024; i += 256) sh[i] = hf[(long)b * 6144 + i];
    __syncthreads();
    int lane = tid & 31, w = tid >> 5;
    for (int p = w; p < 24; p += 8) {
        int h = p / 6, n = p % 6;
        float ss = 0.f, dd = 0.f;
        const float* hv = &sh[n * 1024 + h * 256];
        for (int d = lane; d < 256; d += 32) {
            float v = hv[d];
            ss += v * as_[h * 256 + d];
            dd += v * ad_[h * 256 + d];
        }
        for (int o = 16; o > 0; o >>= 1) {
            ss += __shfl_xor_sync(0xffffffffu, ss, o);
            dd += __shfl_xor_sync(0xffffffffu, dd, o);
        }
        if (lane == 0) { s_src[h][n] = ss; s_dst[h][n] = dd; }
    }
    __syncthreads();
    if (tid < 24) {
        int h = tid / 6, i = tid % 6;
        float e[6]; float mx = -1e30f;
#pragma unroll
        for (int j = 0; j < 6; j++) {
            float x = s_src[h][i] + s_dst[h][j];
            x = (x >= 0.f) ? x : 0.2f * x;
            e[j] = x; mx = fmaxf(mx, x);
        }
        float sum = 0.f;
#pragma unroll
        for (int j = 0; j < 6; j++) { e[j] = expf(e[j] - mx); sum += e[j]; }
        float inv = 1.f / sum;
#pragma unroll
        for (int j = 0; j < 6; j++) s_att[h][i][j] = e[j] * inv;
    }
    __syncthreads();
    for (int o = tid; o < 6 * 1024; o += 256) {
        int i = o >> 10; int hd = o & 1023; int h = hd >> 8;
        float acc = 0.f;
#pragma unroll
        for (int j = 0; j < 6; j++) acc += s_att[h][i][j] * sh[j * 1024 + hd];
        gout[(long)b * 6144 + o] = (acc > 0.f) ? acc : expm1f(acc);
    }
}

// ---------------- per-type MLP head (one block per batch) --------------------------
__global__ void head_kernel(const float* __restrict__ g1, const float* __restrict__ Wa1,
                            const float* __restrict__ ba1, const float* __restrict__ Wa2,
                            const float* __restrict__ ba2, const int* __restrict__ types,
                            float* __restrict__ logits) {
    __shared__ float f0[1024];
    __shared__ float h1[512];
    int b = blockIdx.x, tid = threadIdx.x;
    int pt = types[b * A_];
    for (int i = tid; i < 1024; i += 256) f0[i] = g1[(long)b * A_ * H_ + i];
    __syncthreads();
    for (int d = tid; d < 512; d += 256) {
        const float* W = Wa1 + (long)pt * 1024 * 512 + d;
        float acc = ba1[pt * 512 + d];
#pragma unroll 4
        for (int f = 0; f < 1024; f++) acc += f0[f] * W[(long)f * 512];
        h1[d] = fmaxf(acc, 0.f);
    }
    __syncthreads();
    if (tid < 52) {
        const float* W2 = Wa2 + (long)pt * 512 * 52;
        float acc = ba2[pt * 52 + tid];
#pragma unroll 4
        for (int f = 0; f < 512; f++) acc += h1[f] * W2[f * 52 + tid];
        logits[b * 52 + tid] = acc;
    }
}

// ---------------- final output: masked logits + hT ---------------------------------
__global__ void final_kernel(const float* __restrict__ inp, const float* __restrict__ hT,
                             const float* __restrict__ logits, float* __restrict__ out) {
    int idx = blockIdx.x * blockDim.x + threadIdx.x;
    if (idx < NLOG) {
        int m = idx % MASK_;
        int bs = idx / MASK_;
        float mask = inp[(long)bs * OBS_ + (OBS_ - MASK_) + m];
        int b = bs / S_;
        out[idx] = (mask != 0.f) ? logits[b * MASK_ + m] : 0.f;
    } else if (idx < NLOG + NSEQ * H_) {
        out[idx] = hT[idx - NLOG];
    }
}

// ---------------- launch ------------------------------------------------------------
extern "C" void kernel_launch(void* const* d_in, const int* in_sizes, int n_in,
                              void* d_out, int out_size) {
    const float* inputs = (const float*)d_in[0];
    const float* state0 = (const float*)d_in[1];
    const float* W_emb  = (const float*)d_in[2];
    const float* b_emb  = (const float*)d_in[3];
    const float* W_ih   = (const float*)d_in[4];
    const float* W_hh   = (const float*)d_in[5];
    const float* b_ih   = (const float*)d_in[6];
    const float* b_hh   = (const float*)d_in[7];
    const float* Wg0    = (const float*)d_in[8];
    const float* a0s    = (const float*)d_in[9];
    const float* a0d    = (const float*)d_in[10];
    const float* Wg1    = (const float*)d_in[11];
    const float* a1s    = (const float*)d_in[12];
    const float* a1d    = (const float*)d_in[13];
    const float* Wa1    = (const float*)d_in[14];
    const float* ba1    = (const float*)d_in[15];
    const float* Wa2    = (const float*)d_in[16];
    const float* ba2    = (const float*)d_in[17];
    float* out = (float*)d_out;

    float *vec, *wemb, *emb, *xg, *ha, *hb, *hf, *g0, *g1, *logits;
    int* types;
    cudaGetSymbolAddress((void**)&vec, g_vec);
    cudaGetSymbolAddress((void**)&wemb, g_wemb);
    cudaGetSymbolAddress((void**)&types, g_types);
    cudaGetSymbolAddress((void**)&emb, g_emb);
    cudaGetSymbolAddress((void**)&xg, g_xg);
    cudaGetSymbolAddress((void**)&ha, g_ha);
    cudaGetSymbolAddress((void**)&hb, g_hb);
    cudaGetSymbolAddress((void**)&hf, g_hf);
    cudaGetSymbolAddress((void**)&g0, g_g0);
    cudaGetSymbolAddress((void**)&g1, g_g1);
    cudaGetSymbolAddress((void**)&logits, g_logits);

    // 1) preprocessing (vec/wemb/h0/types + W_hh permute + barrier reset)
    {
        long total = (long)NSEQ * S_ * KVEC + 5L * KVEC * EMBD + (long)NSEQ * H_ + NSEQ
                   + 3L * H_ * H_ + 1;
        prep_kernel<<<(unsigned)((total + 255) / 256), 256>>>(inputs, state0, W_emb, W_hh);
    }
    // 2) emb = relu(vec @ W_emb[type] + b_emb[type])
    gemm_kernel<64, 128, 4, 8, false, true, false, true>
        <<<dim3(EMBD / 128, MROWS / 64), 256>>>(vec, wemb, b_emb, emb,
            MROWS, EMBD, KVEC, KVEC, EMBD, EMBD, types, (long)KVEC * EMBD, EMBD);
    // 3) xg = emb @ W_ih^T + b_ih -> step-major
    gemm_kernel<64, 128, 4, 8, true, false, true, false>
        <<<dim3(G3H / 128, MROWS / 64), 256>>>(emb, W_ih, b_ih, xg,
            MROWS, G3H, EMBD, EMBD, EMBD, G3H, nullptr, 0, 0);
    // 4) GRU: one persistent kernel, 256 fused steps (hT ends in ha)
    gru_persistent<<<NBLK, 256>>>(xg, b_hh, ha, hb);
    float* hT = ha;
    // 5) GAT layer 0
    gemm_kernel<64, 64, 4, 4, false, false, false, false>
        <<<dim3(H_ / 64, NSEQ / 64), 256>>>(hT, Wg0, nullptr, hf,
            NSEQ, H_, H_, H_, H_, H_, nullptr, 0, 0);
    gat_attn_kernel<<<B_, 256>>>(hf, a0s, a0d, g0);
    // 6) GAT layer 1
    gemm_kernel<64, 64, 4, 4, false, false, false, false>
        <<<dim3(H_ / 64, NSEQ / 64), 256>>>(g0, Wg1, nullptr, hf,
            NSEQ, H_, H_, H_, H_, H_, nullptr, 0, 0);
    gat_attn_kernel<<<B_, 256>>>(hf, a1s, a1d, g1);
    // 7) head
    head_kernel<<<B_, 256>>>(g1, Wa1, ba1, Wa2, ba2, types, logits);
    // 8) output assembly
    {
        int total = NLOG + NSEQ * H_;
        final_kernel<<<(total + 255) / 256, 256>>>(inputs, hT, logits, out);
    }
}